// round 4
// baseline (speedup 1.0000x reference)
#include <cuda_runtime.h>
#include <cstdint>
#include <cstddef>

#define T_STEPS 32768
#define OBS 128
#define ACT 32
#define LAT 512
#define HID 1024
#define G3  3072
#define XDIM 544
#define NCTA 128

// ---------------- scratch (device globals; no allocation allowed) ----------------
__device__ float g_x[(size_t)T_STEPS * XDIM];    // [T,544] = [tanh(enc), a_prev]
__device__ float g_gi[(size_t)T_STEPS * G3];     // [T,3072] input-side gate preacts
__device__ float g_hex[2][HID];                  // double-buffered h exchange
__device__ int   g_flags[NCTA];                  // per-CTA step counters

// ---------------- math helpers ----------------
__device__ __forceinline__ float fsig(float x) {
    return 1.0f / (1.0f + __expf(-x));
}
__device__ __forceinline__ float ftanh(float x) {
    float ax = fabsf(x);
    float e  = __expf(2.0f * ax);
    float r  = 1.0f - 2.0f / (e + 1.0f);
    return copysignf(r, x);
}
__device__ __forceinline__ int ld_acquire_gpu(const int* p) {
    int v;
    asm volatile("ld.acquire.gpu.global.s32 %0, [%1];" : "=r"(v) : "l"(p) : "memory");
    return v;
}
__device__ __forceinline__ void st_release_gpu(int* p, int v) {
    asm volatile("st.release.gpu.global.s32 [%0], %1;" :: "l"(p), "r"(v) : "memory");
}
__device__ __forceinline__ void st_cg_f32(float* p, float v) {
    asm volatile("st.global.cg.f32 [%0], %1;" :: "l"(p), "f"(v) : "memory");
}
__device__ __forceinline__ void fence_acqrel_gpu() {
    asm volatile("fence.acq_rel.gpu;" ::: "memory");
}

// ---------------- init: zero sync flags (must run every launch/replay) ----------------
__global__ void init_kernel() {
    int i = threadIdx.x;
    if (i < NCTA) g_flags[i] = 0;
}

// ---------------- encoder: z = tanh(obs @ enc_w^T + enc_b) -> g_x[:, :512] ----------------
// (round-1 proven)
__global__ void __launch_bounds__(256) enc_kernel(const float* __restrict__ obs,
                                                  const float* __restrict__ enc_w,
                                                  const float* __restrict__ enc_b) {
    __shared__ float so[64 * 65];   // [t][k] padded
    __shared__ float sw[64 * 65];   // [l][k] padded

    const int tid = threadIdx.x;
    const int tx = tid & 15;
    const int ty = tid >> 4;
    const int t0 = blockIdx.x * 64;

    for (int l0 = 0; l0 < LAT; l0 += 64) {
        float acc[4][4];
#pragma unroll
        for (int i = 0; i < 4; i++)
#pragma unroll
            for (int j = 0; j < 4; j++) acc[i][j] = 0.0f;

        for (int k0 = 0; k0 < OBS; k0 += 64) {
            __syncthreads();
#pragma unroll
            for (int v = 0; v < 4; v++) {
                int idx = tid + 256 * v;
                int row = idx >> 4;
                int c4  = idx & 15;
                float4 a = *reinterpret_cast<const float4*>(
                    &obs[(size_t)(t0 + row) * OBS + k0 + c4 * 4]);
                float* d = &so[row * 65 + c4 * 4];
                d[0] = a.x; d[1] = a.y; d[2] = a.z; d[3] = a.w;
                float4 b = *reinterpret_cast<const float4*>(
                    &enc_w[(size_t)(l0 + row) * OBS + k0 + c4 * 4]);
                float* e = &sw[row * 65 + c4 * 4];
                e[0] = b.x; e[1] = b.y; e[2] = b.z; e[3] = b.w;
            }
            __syncthreads();
#pragma unroll 8
            for (int k = 0; k < 64; k++) {
                float a[4], b[4];
#pragma unroll
                for (int i = 0; i < 4; i++) a[i] = so[(ty * 4 + i) * 65 + k];
#pragma unroll
                for (int j = 0; j < 4; j++) b[j] = sw[(tx * 4 + j) * 65 + k];
#pragma unroll
                for (int i = 0; i < 4; i++)
#pragma unroll
                    for (int j = 0; j < 4; j++)
                        acc[i][j] = fmaf(a[i], b[j], acc[i][j]);
            }
        }
#pragma unroll
        for (int j = 0; j < 4; j++) {
            int l = l0 + tx * 4 + j;
            float bb = enc_b[l];
#pragma unroll
            for (int i = 0; i < 4; i++) {
                int t = t0 + ty * 4 + i;
                g_x[(size_t)t * XDIM + l] = ftanh(acc[i][j] + bb);
            }
        }
    }
}

// ---------------- pack shifted actions -> g_x[:, 512:544] ----------------
__global__ void pack_act(const float* __restrict__ act) {
    int idx = blockIdx.x * blockDim.x + threadIdx.x;
    int t = idx >> 5, c = idx & 31;
    g_x[(size_t)t * XDIM + LAT + c] = (t == 0) ? 0.0f : act[(size_t)(t - 1) * ACT + c];
}

// ---------------- gi GEMM: g_gi = g_x @ w_ih^T + b_ih ----------------
// (round-1 proven) BM=64 BN=128 BK=16, 256 threads, thread tile 4x8
__global__ void __launch_bounds__(256) gemm_gi(const float* __restrict__ W,
                                               const float* __restrict__ bias) {
    __shared__ __align__(16) float Xs[16][68];    // [k][m]
    __shared__ __align__(16) float Ws[16][132];   // [k][n]

    const int tid = threadIdx.x;
    const int tx = tid & 15;        // n: 8 each
    const int ty = tid >> 4;        // m: 4 each
    const int m0 = blockIdx.y * 64;
    const int n0 = blockIdx.x * 128;

    const int xrow = tid >> 2;      // 0..63
    const int k4   = tid & 3;       // 0..3 (float4 group)

    float acc[4][8];
#pragma unroll
    for (int i = 0; i < 4; i++)
#pragma unroll
        for (int j = 0; j < 8; j++) acc[i][j] = 0.0f;

    for (int k0 = 0; k0 < XDIM; k0 += 16) {
        float4 xv = *reinterpret_cast<const float4*>(
            &g_x[(size_t)(m0 + xrow) * XDIM + k0 + k4 * 4]);
        float4 wv0 = *reinterpret_cast<const float4*>(
            &W[(size_t)(n0 + xrow) * XDIM + k0 + k4 * 4]);
        float4 wv1 = *reinterpret_cast<const float4*>(
            &W[(size_t)(n0 + 64 + xrow) * XDIM + k0 + k4 * 4]);
        __syncthreads();
        int kb = k4 * 4;
        Xs[kb + 0][xrow] = xv.x; Xs[kb + 1][xrow] = xv.y;
        Xs[kb + 2][xrow] = xv.z; Xs[kb + 3][xrow] = xv.w;
        Ws[kb + 0][xrow] = wv0.x; Ws[kb + 1][xrow] = wv0.y;
        Ws[kb + 2][xrow] = wv0.z; Ws[kb + 3][xrow] = wv0.w;
        Ws[kb + 0][64 + xrow] = wv1.x; Ws[kb + 1][64 + xrow] = wv1.y;
        Ws[kb + 2][64 + xrow] = wv1.z; Ws[kb + 3][64 + xrow] = wv1.w;
        __syncthreads();
#pragma unroll
        for (int k = 0; k < 16; k++) {
            float4 av  = *reinterpret_cast<const float4*>(&Xs[k][ty * 4]);
            float4 bv0 = *reinterpret_cast<const float4*>(&Ws[k][tx * 8]);
            float4 bv1 = *reinterpret_cast<const float4*>(&Ws[k][tx * 8 + 4]);
            float a[4] = {av.x, av.y, av.z, av.w};
            float b[8] = {bv0.x, bv0.y, bv0.z, bv0.w, bv1.x, bv1.y, bv1.z, bv1.w};
#pragma unroll
            for (int i = 0; i < 4; i++)
#pragma unroll
                for (int j = 0; j < 8; j++)
                    acc[i][j] = fmaf(a[i], b[j], acc[i][j]);
        }
    }
    float bb[8];
#pragma unroll
    for (int j = 0; j < 8; j++) bb[j] = bias[n0 + tx * 8 + j];
#pragma unroll
    for (int i = 0; i < 4; i++) {
        size_t base = (size_t)(m0 + ty * 4 + i) * G3 + n0 + tx * 8;
        float4 o0 = {acc[i][0] + bb[0], acc[i][1] + bb[1], acc[i][2] + bb[2], acc[i][3] + bb[3]};
        float4 o1 = {acc[i][4] + bb[4], acc[i][5] + bb[5], acc[i][6] + bb[6], acc[i][7] + bb[7]};
        *reinterpret_cast<float4*>(&g_gi[base])     = o0;
        *reinterpret_cast<float4*>(&g_gi[base + 4]) = o1;
    }
}

// ---------------- persistent GRU recurrence ----------------
// 128 CTAs x 256 thr. Warp w of CTA b owns hidden element j = b*8 + w.
// Round-1 flag protocol with cheap fences:
//   producer: st.cg h -> fence.acq_rel.gpu -> bar -> tid0 st.release flag
//   consumer: all warps poll flags with ld.acquire -> stage h (ld.cg) -> bar
__global__ void __launch_bounds__(256, 1) recur_kernel(const float* __restrict__ whh,
                                                       const float* __restrict__ bhh,
                                                       float* __restrict__ out) {
    __shared__ __align__(16) float hs[HID];

    const int tid  = threadIdx.x;
    const int lane = tid & 31;
    const int wid  = tid >> 5;
    const int bid  = blockIdx.x;
    const int j    = bid * 8 + wid;

    // resident weights (round-1 layout)
    float wr[32], wz[32], wn[32];
    {
        const float4* pr = reinterpret_cast<const float4*>(whh + (size_t)(0 * HID + j) * HID);
        const float4* pz = reinterpret_cast<const float4*>(whh + (size_t)(1 * HID + j) * HID);
        const float4* pn = reinterpret_cast<const float4*>(whh + (size_t)(2 * HID + j) * HID);
#pragma unroll
        for (int i = 0; i < 8; i++) {
            float4 v;
            v = pr[lane + 32 * i]; wr[4*i]=v.x; wr[4*i+1]=v.y; wr[4*i+2]=v.z; wr[4*i+3]=v.w;
            v = pz[lane + 32 * i]; wz[4*i]=v.x; wz[4*i+1]=v.y; wz[4*i+2]=v.z; wz[4*i+3]=v.w;
            v = pn[lane + 32 * i]; wn[4*i]=v.x; wn[4*i+1]=v.y; wn[4*i+2]=v.z; wn[4*i+3]=v.w;
        }
    }
    const float br = bhh[j], bz = bhh[HID + j], bn = bhh[2 * HID + j];

    for (int i = tid; i < HID; i += 256) hs[i] = 0.0f;
    __syncthreads();

    // gi for t=0
    float gr = g_gi[j], gz = g_gi[HID + j], gn = g_gi[2 * HID + j];

    for (int t = 0; t < T_STEPS; t++) {
        // prefetch next step's gi (independent of the wait)
        float ngr = 0.f, ngz = 0.f, ngn = 0.f;
        if (t + 1 < T_STEPS) {
            const float* p = g_gi + (size_t)(t + 1) * G3;
            ngr = __ldg(p + j); ngz = __ldg(p + HID + j); ngn = __ldg(p + 2 * HID + j);
        }

        if (t > 0) {
            // every warp polls all 128 flags (4 per lane) with acquire loads
            for (;;) {
                int f0 = ld_acquire_gpu(&g_flags[lane]);
                int f1 = ld_acquire_gpu(&g_flags[lane + 32]);
                int f2 = ld_acquire_gpu(&g_flags[lane + 64]);
                int f3 = ld_acquire_gpu(&g_flags[lane + 96]);
                int m = min(min(f0, f1), min(f2, f3));
                if (__all_sync(0xffffffffu, m >= t)) break;
            }
            // stage h_t (L1 bypass: written by other SMs)
            const float4* src = reinterpret_cast<const float4*>(g_hex[t & 1]);
            reinterpret_cast<float4*>(hs)[tid] = __ldcg(src + tid);
            __syncthreads();   // all warps staged before anyone reads full hs
        }

        // 3 dot products of length 1024 (round-1-proven scalar FFMA)
        float ar = 0.f, az = 0.f, an = 0.f;
        const float4* h4 = reinterpret_cast<const float4*>(hs);
#pragma unroll
        for (int i = 0; i < 8; i++) {
            float4 hv = h4[lane + 32 * i];
            ar = fmaf(wr[4*i  ], hv.x, ar); ar = fmaf(wr[4*i+1], hv.y, ar);
            ar = fmaf(wr[4*i+2], hv.z, ar); ar = fmaf(wr[4*i+3], hv.w, ar);
            az = fmaf(wz[4*i  ], hv.x, az); az = fmaf(wz[4*i+1], hv.y, az);
            az = fmaf(wz[4*i+2], hv.z, az); az = fmaf(wz[4*i+3], hv.w, az);
            an = fmaf(wn[4*i  ], hv.x, an); an = fmaf(wn[4*i+1], hv.y, an);
            an = fmaf(wn[4*i+2], hv.z, an); an = fmaf(wn[4*i+3], hv.w, an);
        }
#pragma unroll
        for (int o = 16; o > 0; o >>= 1) {
            ar += __shfl_xor_sync(0xffffffffu, ar, o);
            az += __shfl_xor_sync(0xffffffffu, az, o);
            an += __shfl_xor_sync(0xffffffffu, an, o);
        }

        float r    = fsig(gr + ar + br);
        float zz   = fsig(gz + az + bz);
        float n    = ftanh(gn + r * (an + bn));
        float hold = hs[j];
        float hnew = n + zz * (hold - n);   // (1-z)*n + z*h

        if (lane == 0) {
            out[(size_t)t * HID + j] = hnew;
            st_cg_f32(&g_hex[(t + 1) & 1][j], hnew);
            fence_acqrel_gpu();              // order my h store before the CTA flag
        }

        gr = ngr; gz = ngz; gn = ngn;

        __syncthreads();                     // all warps published + fenced
        if (tid == 0) {
            st_release_gpu(&g_flags[bid], t + 1);   // release: flag after h stores
        }
    }
}

// ---------------- launch ----------------
extern "C" void kernel_launch(void* const* d_in, const int* in_sizes, int n_in,
                              void* d_out, int out_size) {
    const float* obs   = (const float*)d_in[0];
    const float* act   = (const float*)d_in[1];
    const float* enc_w = (const float*)d_in[2];
    const float* enc_b = (const float*)d_in[3];
    const float* w_ih  = (const float*)d_in[4];
    const float* w_hh  = (const float*)d_in[5];
    const float* b_ih  = (const float*)d_in[6];
    const float* b_hh  = (const float*)d_in[7];
    float* out = (float*)d_out;

    init_kernel<<<1, 128>>>();
    enc_kernel<<<T_STEPS / 64, 256>>>(obs, enc_w, enc_b);
    pack_act<<<(T_STEPS * ACT) / 256, 256>>>(act);
    gemm_gi<<<dim3(G3 / 128, T_STEPS / 64), 256>>>(w_ih, b_ih);
    recur_kernel<<<NCTA, 256>>>(w_hh, b_hh, out);
}

// round 11
// speedup vs baseline: 1.3590x; 1.3590x over previous
#include <cuda_runtime.h>
#include <cstdint>
#include <cstddef>

#define T_STEPS 32768
#define OBS 128
#define ACT 32
#define LAT 512
#define HID 1024
#define G3  3072
#define XDIM 544
#define NCTA 128

// ---------------- scratch (device globals; no allocation allowed) ----------------
__device__ float g_x[(size_t)T_STEPS * XDIM];    // [T,544] = [tanh(enc), a_prev]
__device__ float g_gi[(size_t)T_STEPS * G3];     // [T,3072] input-side gate preacts
__device__ float g_hex[2][HID];                  // double-buffered h exchange
__device__ int   g_flags[NCTA];                  // per-CTA step counters

// ---------------- math helpers ----------------
__device__ __forceinline__ float fsig(float x) {
    return 1.0f / (1.0f + __expf(-x));
}
__device__ __forceinline__ float ftanh(float x) {
    float ax = fabsf(x);
    float e  = __expf(2.0f * ax);
    float r  = 1.0f - 2.0f / (e + 1.0f);
    return copysignf(r, x);
}
__device__ __forceinline__ int ld_acquire_gpu(const int* p) {
    int v;
    asm volatile("ld.acquire.gpu.global.s32 %0, [%1];" : "=r"(v) : "l"(p) : "memory");
    return v;
}
__device__ __forceinline__ void st_release_gpu(int* p, int v) {
    asm volatile("st.release.gpu.global.s32 [%0], %1;" :: "l"(p), "r"(v) : "memory");
}
__device__ __forceinline__ void st_cg_f32(float* p, float v) {
    asm volatile("st.global.cg.f32 [%0], %1;" :: "l"(p), "f"(v) : "memory");
}
__device__ __forceinline__ void fence_acqrel_gpu() {
    asm volatile("fence.acq_rel.gpu;" ::: "memory");
}

// ---------------- init: zero sync flags (must run every launch/replay) ----------------
__global__ void init_kernel() {
    int i = threadIdx.x;
    if (i < NCTA) g_flags[i] = 0;
}

// ---------------- encoder: z = tanh(obs @ enc_w^T + enc_b) -> g_x[:, :512] ----------------
// (round-1 proven)
__global__ void __launch_bounds__(256) enc_kernel(const float* __restrict__ obs,
                                                  const float* __restrict__ enc_w,
                                                  const float* __restrict__ enc_b) {
    __shared__ float so[64 * 65];   // [t][k] padded
    __shared__ float sw[64 * 65];   // [l][k] padded

    const int tid = threadIdx.x;
    const int tx = tid & 15;
    const int ty = tid >> 4;
    const int t0 = blockIdx.x * 64;

    for (int l0 = 0; l0 < LAT; l0 += 64) {
        float acc[4][4];
#pragma unroll
        for (int i = 0; i < 4; i++)
#pragma unroll
            for (int j = 0; j < 4; j++) acc[i][j] = 0.0f;

        for (int k0 = 0; k0 < OBS; k0 += 64) {
            __syncthreads();
#pragma unroll
            for (int v = 0; v < 4; v++) {
                int idx = tid + 256 * v;
                int row = idx >> 4;
                int c4  = idx & 15;
                float4 a = *reinterpret_cast<const float4*>(
                    &obs[(size_t)(t0 + row) * OBS + k0 + c4 * 4]);
                float* d = &so[row * 65 + c4 * 4];
                d[0] = a.x; d[1] = a.y; d[2] = a.z; d[3] = a.w;
                float4 b = *reinterpret_cast<const float4*>(
                    &enc_w[(size_t)(l0 + row) * OBS + k0 + c4 * 4]);
                float* e = &sw[row * 65 + c4 * 4];
                e[0] = b.x; e[1] = b.y; e[2] = b.z; e[3] = b.w;
            }
            __syncthreads();
#pragma unroll 8
            for (int k = 0; k < 64; k++) {
                float a[4], b[4];
#pragma unroll
                for (int i = 0; i < 4; i++) a[i] = so[(ty * 4 + i) * 65 + k];
#pragma unroll
                for (int j = 0; j < 4; j++) b[j] = sw[(tx * 4 + j) * 65 + k];
#pragma unroll
                for (int i = 0; i < 4; i++)
#pragma unroll
                    for (int j = 0; j < 4; j++)
                        acc[i][j] = fmaf(a[i], b[j], acc[i][j]);
            }
        }
#pragma unroll
        for (int j = 0; j < 4; j++) {
            int l = l0 + tx * 4 + j;
            float bb = enc_b[l];
#pragma unroll
            for (int i = 0; i < 4; i++) {
                int t = t0 + ty * 4 + i;
                g_x[(size_t)t * XDIM + l] = ftanh(acc[i][j] + bb);
            }
        }
    }
}

// ---------------- pack shifted actions -> g_x[:, 512:544] ----------------
__global__ void pack_act(const float* __restrict__ act) {
    int idx = blockIdx.x * blockDim.x + threadIdx.x;
    int t = idx >> 5, c = idx & 31;
    g_x[(size_t)t * XDIM + LAT + c] = (t == 0) ? 0.0f : act[(size_t)(t - 1) * ACT + c];
}

// ---------------- gi GEMM: g_gi = g_x @ w_ih^T + b_ih ----------------
// (round-1 proven) BM=64 BN=128 BK=16, 256 threads, thread tile 4x8
__global__ void __launch_bounds__(256) gemm_gi(const float* __restrict__ W,
                                               const float* __restrict__ bias) {
    __shared__ __align__(16) float Xs[16][68];    // [k][m]
    __shared__ __align__(16) float Ws[16][132];   // [k][n]

    const int tid = threadIdx.x;
    const int tx = tid & 15;        // n: 8 each
    const int ty = tid >> 4;        // m: 4 each
    const int m0 = blockIdx.y * 64;
    const int n0 = blockIdx.x * 128;

    const int xrow = tid >> 2;      // 0..63
    const int k4   = tid & 3;       // 0..3 (float4 group)

    float acc[4][8];
#pragma unroll
    for (int i = 0; i < 4; i++)
#pragma unroll
        for (int j = 0; j < 8; j++) acc[i][j] = 0.0f;

    for (int k0 = 0; k0 < XDIM; k0 += 16) {
        float4 xv = *reinterpret_cast<const float4*>(
            &g_x[(size_t)(m0 + xrow) * XDIM + k0 + k4 * 4]);
        float4 wv0 = *reinterpret_cast<const float4*>(
            &W[(size_t)(n0 + xrow) * XDIM + k0 + k4 * 4]);
        float4 wv1 = *reinterpret_cast<const float4*>(
            &W[(size_t)(n0 + 64 + xrow) * XDIM + k0 + k4 * 4]);
        __syncthreads();
        int kb = k4 * 4;
        Xs[kb + 0][xrow] = xv.x; Xs[kb + 1][xrow] = xv.y;
        Xs[kb + 2][xrow] = xv.z; Xs[kb + 3][xrow] = xv.w;
        Ws[kb + 0][xrow] = wv0.x; Ws[kb + 1][xrow] = wv0.y;
        Ws[kb + 2][xrow] = wv0.z; Ws[kb + 3][xrow] = wv0.w;
        Ws[kb + 0][64 + xrow] = wv1.x; Ws[kb + 1][64 + xrow] = wv1.y;
        Ws[kb + 2][64 + xrow] = wv1.z; Ws[kb + 3][64 + xrow] = wv1.w;
        __syncthreads();
#pragma unroll
        for (int k = 0; k < 16; k++) {
            float4 av  = *reinterpret_cast<const float4*>(&Xs[k][ty * 4]);
            float4 bv0 = *reinterpret_cast<const float4*>(&Ws[k][tx * 8]);
            float4 bv1 = *reinterpret_cast<const float4*>(&Ws[k][tx * 8 + 4]);
            float a[4] = {av.x, av.y, av.z, av.w};
            float b[8] = {bv0.x, bv0.y, bv0.z, bv0.w, bv1.x, bv1.y, bv1.z, bv1.w};
#pragma unroll
            for (int i = 0; i < 4; i++)
#pragma unroll
                for (int j = 0; j < 8; j++)
                    acc[i][j] = fmaf(a[i], b[j], acc[i][j]);
        }
    }
    float bb[8];
#pragma unroll
    for (int j = 0; j < 8; j++) bb[j] = bias[n0 + tx * 8 + j];
#pragma unroll
    for (int i = 0; i < 4; i++) {
        size_t base = (size_t)(m0 + ty * 4 + i) * G3 + n0 + tx * 8;
        float4 o0 = {acc[i][0] + bb[0], acc[i][1] + bb[1], acc[i][2] + bb[2], acc[i][3] + bb[3]};
        float4 o1 = {acc[i][4] + bb[4], acc[i][5] + bb[5], acc[i][6] + bb[6], acc[i][7] + bb[7]};
        *reinterpret_cast<float4*>(&g_gi[base])     = o0;
        *reinterpret_cast<float4*>(&g_gi[base + 4]) = o1;
    }
}

// ---------------- persistent GRU recurrence ----------------
// 128 CTAs x 256 thr. Warp w of CTA b owns hidden element j = b*8 + w.
// Sync = intersection of the two proven protocols:
//   producer: lane0 st.cg h publish -> bar -> tid0 {fence.acq_rel.gpu; st.release flag}
//   consumer: warp0-only acquire-poll of 128 flags -> bar -> __ldcg staging -> bar
__global__ void __launch_bounds__(256, 1) recur_kernel(const float* __restrict__ whh,
                                                       const float* __restrict__ bhh,
                                                       float* __restrict__ out) {
    __shared__ __align__(16) float hs[HID];

    const int tid  = threadIdx.x;
    const int lane = tid & 31;
    const int wid  = tid >> 5;
    const int bid  = blockIdx.x;
    const int j    = bid * 8 + wid;

    // resident weights (round-1 layout)
    float wr[32], wz[32], wn[32];
    {
        const float4* pr = reinterpret_cast<const float4*>(whh + (size_t)(0 * HID + j) * HID);
        const float4* pz = reinterpret_cast<const float4*>(whh + (size_t)(1 * HID + j) * HID);
        const float4* pn = reinterpret_cast<const float4*>(whh + (size_t)(2 * HID + j) * HID);
#pragma unroll
        for (int i = 0; i < 8; i++) {
            float4 v;
            v = pr[lane + 32 * i]; wr[4*i]=v.x; wr[4*i+1]=v.y; wr[4*i+2]=v.z; wr[4*i+3]=v.w;
            v = pz[lane + 32 * i]; wz[4*i]=v.x; wz[4*i+1]=v.y; wz[4*i+2]=v.z; wz[4*i+3]=v.w;
            v = pn[lane + 32 * i]; wn[4*i]=v.x; wn[4*i+1]=v.y; wn[4*i+2]=v.z; wn[4*i+3]=v.w;
        }
    }
    const float br = bhh[j], bz = bhh[HID + j], bn = bhh[2 * HID + j];

    for (int i = tid; i < HID; i += 256) hs[i] = 0.0f;
    __syncthreads();

    // gi for t=0
    float gr = g_gi[j], gz = g_gi[HID + j], gn = g_gi[2 * HID + j];

    for (int t = 0; t < T_STEPS; t++) {
        // prefetch next step's gi (independent of the wait)
        float ngr = 0.f, ngz = 0.f, ngn = 0.f;
        if (t + 1 < T_STEPS) {
            const float* p = g_gi + (size_t)(t + 1) * G3;
            ngr = __ldg(p + j); ngz = __ldg(p + HID + j); ngn = __ldg(p + 2 * HID + j);
        }

        if (t > 0) {
            if (wid == 0) {
                // only warp 0 polls (4 flags per lane) with acquire loads
                for (;;) {
                    int f0 = ld_acquire_gpu(&g_flags[lane]);
                    int f1 = ld_acquire_gpu(&g_flags[lane + 32]);
                    int f2 = ld_acquire_gpu(&g_flags[lane + 64]);
                    int f3 = ld_acquire_gpu(&g_flags[lane + 96]);
                    int m = min(min(f0, f1), min(f2, f3));
                    if (__all_sync(0xffffffffu, m >= t)) break;
                }
            }
            __syncthreads();   // broadcast detection (hb: release -> acquire -> bar)
            // stage h_t (L1 bypass: written by other SMs)
            const float4* src = reinterpret_cast<const float4*>(g_hex[t & 1]);
            reinterpret_cast<float4*>(hs)[tid] = __ldcg(src + tid);
            __syncthreads();   // all warps staged before anyone reads full hs
        }

        // 3 dot products of length 1024 (round-1-proven scalar FFMA)
        float ar = 0.f, az = 0.f, an = 0.f;
        const float4* h4 = reinterpret_cast<const float4*>(hs);
#pragma unroll
        for (int i = 0; i < 8; i++) {
            float4 hv = h4[lane + 32 * i];
            ar = fmaf(wr[4*i  ], hv.x, ar); ar = fmaf(wr[4*i+1], hv.y, ar);
            ar = fmaf(wr[4*i+2], hv.z, ar); ar = fmaf(wr[4*i+3], hv.w, ar);
            az = fmaf(wz[4*i  ], hv.x, az); az = fmaf(wz[4*i+1], hv.y, az);
            az = fmaf(wz[4*i+2], hv.z, az); az = fmaf(wz[4*i+3], hv.w, az);
            an = fmaf(wn[4*i  ], hv.x, an); an = fmaf(wn[4*i+1], hv.y, an);
            an = fmaf(wn[4*i+2], hv.z, an); an = fmaf(wn[4*i+3], hv.w, an);
        }
#pragma unroll
        for (int o = 16; o > 0; o >>= 1) {
            ar += __shfl_xor_sync(0xffffffffu, ar, o);
            az += __shfl_xor_sync(0xffffffffu, az, o);
            an += __shfl_xor_sync(0xffffffffu, an, o);
        }

        float r    = fsig(gr + ar + br);
        float zz   = fsig(gz + az + bz);
        float n    = ftanh(gn + r * (an + bn));
        float hold = hs[j];
        float hnew = n + zz * (hold - n);   // (1-z)*n + z*h

        if (lane == 0) {
            out[(size_t)t * HID + j] = hnew;
            st_cg_f32(&g_hex[(t + 1) & 1][j], hnew);
        }

        gr = ngr; gz = ngz; gn = ngn;

        __syncthreads();                     // all warps published
        if (tid == 0) {
            fence_acqrel_gpu();              // order CTA's h stores (hb via bar)
            st_release_gpu(&g_flags[bid], t + 1);
        }
    }
}

// ---------------- launch ----------------
extern "C" void kernel_launch(void* const* d_in, const int* in_sizes, int n_in,
                              void* d_out, int out_size) {
    const float* obs   = (const float*)d_in[0];
    const float* act   = (const float*)d_in[1];
    const float* enc_w = (const float*)d_in[2];
    const float* enc_b = (const float*)d_in[3];
    const float* w_ih  = (const float*)d_in[4];
    const float* w_hh  = (const float*)d_in[5];
    const float* b_ih  = (const float*)d_in[6];
    const float* b_hh  = (const float*)d_in[7];
    float* out = (float*)d_out;

    init_kernel<<<1, 128>>>();
    enc_kernel<<<T_STEPS / 64, 256>>>(obs, enc_w, enc_b);
    pack_act<<<(T_STEPS * ACT) / 256, 256>>>(act);
    gemm_gi<<<dim3(G3 / 128, T_STEPS / 64), 256>>>(w_ih, b_ih);
    recur_kernel<<<NCTA, 256>>>(w_hh, b_hh, out);
}

// round 17
// speedup vs baseline: 1.9914x; 1.4653x over previous
#include <cuda_runtime.h>
#include <cstdint>
#include <cstddef>

#define T_STEPS 32768
#define OBS 128
#define ACT 32
#define LAT 512
#define HID 1024
#define G3  3072
#define XDIM 544
#define NCTA 128

// ---------------- scratch (device globals; no allocation allowed) ----------------
__device__ float g_x[(size_t)T_STEPS * XDIM];    // [T,544] = [tanh(enc), a_prev]
__device__ float g_gi[(size_t)T_STEPS * G3];     // [T,3072] input-side gate preacts
__device__ float g_hex[2][HID];                  // double-buffered h exchange
__device__ int   g_flags[NCTA];                  // per-CTA step counters

// ---------------- math helpers ----------------
__device__ __forceinline__ float fsig(float x) {
    return 1.0f / (1.0f + __expf(-x));
}
__device__ __forceinline__ float ftanh(float x) {
    float ax = fabsf(x);
    float e  = __expf(2.0f * ax);
    float r  = 1.0f - 2.0f / (e + 1.0f);
    return copysignf(r, x);
}
// packed f32x2 fused multiply-add: d = a*b + c elementwise on float pairs
__device__ __forceinline__ unsigned long long ffma2(unsigned long long a,
                                                    unsigned long long b,
                                                    unsigned long long c) {
    unsigned long long d;
    asm("fma.rn.f32x2 %0, %1, %2, %3;" : "=l"(d) : "l"(a), "l"(b), "l"(c));
    return d;
}
__device__ __forceinline__ float2 unpack2(unsigned long long v) {
    float2 f;
    asm("mov.b64 {%0, %1}, %2;" : "=f"(f.x), "=f"(f.y) : "l"(v));
    return f;
}

// ---------------- init: zero sync flags (must run every launch/replay) ----------------
__global__ void init_kernel() {
    int i = threadIdx.x;
    if (i < NCTA) g_flags[i] = 0;
}

// ---------------- encoder: z = tanh(obs @ enc_w^T + enc_b) -> g_x[:, :512] ----------------
// (round-1 proven)
__global__ void __launch_bounds__(256) enc_kernel(const float* __restrict__ obs,
                                                  const float* __restrict__ enc_w,
                                                  const float* __restrict__ enc_b) {
    __shared__ float so[64 * 65];   // [t][k] padded
    __shared__ float sw[64 * 65];   // [l][k] padded

    const int tid = threadIdx.x;
    const int tx = tid & 15;
    const int ty = tid >> 4;
    const int t0 = blockIdx.x * 64;

    for (int l0 = 0; l0 < LAT; l0 += 64) {
        float acc[4][4];
#pragma unroll
        for (int i = 0; i < 4; i++)
#pragma unroll
            for (int j = 0; j < 4; j++) acc[i][j] = 0.0f;

        for (int k0 = 0; k0 < OBS; k0 += 64) {
            __syncthreads();
#pragma unroll
            for (int v = 0; v < 4; v++) {
                int idx = tid + 256 * v;
                int row = idx >> 4;
                int c4  = idx & 15;
                float4 a = *reinterpret_cast<const float4*>(
                    &obs[(size_t)(t0 + row) * OBS + k0 + c4 * 4]);
                float* d = &so[row * 65 + c4 * 4];
                d[0] = a.x; d[1] = a.y; d[2] = a.z; d[3] = a.w;
                float4 b = *reinterpret_cast<const float4*>(
                    &enc_w[(size_t)(l0 + row) * OBS + k0 + c4 * 4]);
                float* e = &sw[row * 65 + c4 * 4];
                e[0] = b.x; e[1] = b.y; e[2] = b.z; e[3] = b.w;
            }
            __syncthreads();
#pragma unroll 8
            for (int k = 0; k < 64; k++) {
                float a[4], b[4];
#pragma unroll
                for (int i = 0; i < 4; i++) a[i] = so[(ty * 4 + i) * 65 + k];
#pragma unroll
                for (int j = 0; j < 4; j++) b[j] = sw[(tx * 4 + j) * 65 + k];
#pragma unroll
                for (int i = 0; i < 4; i++)
#pragma unroll
                    for (int j = 0; j < 4; j++)
                        acc[i][j] = fmaf(a[i], b[j], acc[i][j]);
            }
        }
#pragma unroll
        for (int j = 0; j < 4; j++) {
            int l = l0 + tx * 4 + j;
            float bb = enc_b[l];
#pragma unroll
            for (int i = 0; i < 4; i++) {
                int t = t0 + ty * 4 + i;
                g_x[(size_t)t * XDIM + l] = ftanh(acc[i][j] + bb);
            }
        }
    }
}

// ---------------- pack shifted actions -> g_x[:, 512:544] ----------------
__global__ void pack_act(const float* __restrict__ act) {
    int idx = blockIdx.x * blockDim.x + threadIdx.x;
    int t = idx >> 5, c = idx & 31;
    g_x[(size_t)t * XDIM + LAT + c] = (t == 0) ? 0.0f : act[(size_t)(t - 1) * ACT + c];
}

// ---------------- gi GEMM: g_gi = g_x @ w_ih^T + b_ih ----------------
// (round-1 proven) BM=64 BN=128 BK=16, 256 threads, thread tile 4x8
__global__ void __launch_bounds__(256) gemm_gi(const float* __restrict__ W,
                                               const float* __restrict__ bias) {
    __shared__ __align__(16) float Xs[16][68];    // [k][m]
    __shared__ __align__(16) float Ws[16][132];   // [k][n]

    const int tid = threadIdx.x;
    const int tx = tid & 15;        // n: 8 each
    const int ty = tid >> 4;        // m: 4 each
    const int m0 = blockIdx.y * 64;
    const int n0 = blockIdx.x * 128;

    const int xrow = tid >> 2;      // 0..63
    const int k4   = tid & 3;       // 0..3 (float4 group)

    float acc[4][8];
#pragma unroll
    for (int i = 0; i < 4; i++)
#pragma unroll
        for (int j = 0; j < 8; j++) acc[i][j] = 0.0f;

    for (int k0 = 0; k0 < XDIM; k0 += 16) {
        float4 xv = *reinterpret_cast<const float4*>(
            &g_x[(size_t)(m0 + xrow) * XDIM + k0 + k4 * 4]);
        float4 wv0 = *reinterpret_cast<const float4*>(
            &W[(size_t)(n0 + xrow) * XDIM + k0 + k4 * 4]);
        float4 wv1 = *reinterpret_cast<const float4*>(
            &W[(size_t)(n0 + 64 + xrow) * XDIM + k0 + k4 * 4]);
        __syncthreads();
        int kb = k4 * 4;
        Xs[kb + 0][xrow] = xv.x; Xs[kb + 1][xrow] = xv.y;
        Xs[kb + 2][xrow] = xv.z; Xs[kb + 3][xrow] = xv.w;
        Ws[kb + 0][xrow] = wv0.x; Ws[kb + 1][xrow] = wv0.y;
        Ws[kb + 2][xrow] = wv0.z; Ws[kb + 3][xrow] = wv0.w;
        Ws[kb + 0][64 + xrow] = wv1.x; Ws[kb + 1][64 + xrow] = wv1.y;
        Ws[kb + 2][64 + xrow] = wv1.z; Ws[kb + 3][64 + xrow] = wv1.w;
        __syncthreads();
#pragma unroll
        for (int k = 0; k < 16; k++) {
            float4 av  = *reinterpret_cast<const float4*>(&Xs[k][ty * 4]);
            float4 bv0 = *reinterpret_cast<const float4*>(&Ws[k][tx * 8]);
            float4 bv1 = *reinterpret_cast<const float4*>(&Ws[k][tx * 8 + 4]);
            float a[4] = {av.x, av.y, av.z, av.w};
            float b[8] = {bv0.x, bv0.y, bv0.z, bv0.w, bv1.x, bv1.y, bv1.z, bv1.w};
#pragma unroll
            for (int i = 0; i < 4; i++)
#pragma unroll
                for (int j = 0; j < 8; j++)
                    acc[i][j] = fmaf(a[i], b[j], acc[i][j]);
        }
    }
    float bb[8];
#pragma unroll
    for (int j = 0; j < 8; j++) bb[j] = bias[n0 + tx * 8 + j];
#pragma unroll
    for (int i = 0; i < 4; i++) {
        size_t base = (size_t)(m0 + ty * 4 + i) * G3 + n0 + tx * 8;
        float4 o0 = {acc[i][0] + bb[0], acc[i][1] + bb[1], acc[i][2] + bb[2], acc[i][3] + bb[3]};
        float4 o1 = {acc[i][4] + bb[4], acc[i][5] + bb[5], acc[i][6] + bb[6], acc[i][7] + bb[7]};
        *reinterpret_cast<float4*>(&g_gi[base])     = o0;
        *reinterpret_cast<float4*>(&g_gi[base + 4]) = o1;
    }
}

// ---------------- persistent GRU recurrence ----------------
// 128 CTAs x 256 thr. Warp w of CTA b owns hidden element j = b*8 + w.
// Sync = EXACT round-1 protocol (fastest proven), minus the consumer-side
// threadfence (staging is ld.cg straight from L2, the coherence point; the
// producer fence already ordered h before flag at L2; no load speculation).
// Compute = f32x2 packed FMA (halves the fma-issue floor; numerics exonerated
// by the R2/R3 bisection which failed identically with scalar compute).
__global__ void __launch_bounds__(256, 1) recur_kernel(const float* __restrict__ whh,
                                                       const float* __restrict__ bhh,
                                                       float* __restrict__ out) {
    __shared__ __align__(16) float hs[HID];

    const int tid  = threadIdx.x;
    const int lane = tid & 31;
    const int wid  = tid >> 5;
    const int bid  = blockIdx.x;
    const int j    = bid * 8 + wid;

    // resident weights as packed f32x2 pairs: 16 u64 per gate
    unsigned long long wr2[16], wz2[16], wn2[16];
    {
        const ulonglong2* pr = reinterpret_cast<const ulonglong2*>(whh + (size_t)(0 * HID + j) * HID);
        const ulonglong2* pz = reinterpret_cast<const ulonglong2*>(whh + (size_t)(1 * HID + j) * HID);
        const ulonglong2* pn = reinterpret_cast<const ulonglong2*>(whh + (size_t)(2 * HID + j) * HID);
#pragma unroll
        for (int i = 0; i < 8; i++) {
            ulonglong2 v;
            v = pr[lane + 32 * i]; wr2[2 * i] = v.x; wr2[2 * i + 1] = v.y;
            v = pz[lane + 32 * i]; wz2[2 * i] = v.x; wz2[2 * i + 1] = v.y;
            v = pn[lane + 32 * i]; wn2[2 * i] = v.x; wn2[2 * i + 1] = v.y;
        }
    }
    const float br = bhh[j], bz = bhh[HID + j], bn = bhh[2 * HID + j];

    for (int i = tid; i < HID; i += 256) hs[i] = 0.0f;
    __syncthreads();

    // gi for t=0
    float gr = g_gi[j], gz = g_gi[HID + j], gn = g_gi[2 * HID + j];

    volatile int* vflags = g_flags;

    for (int t = 0; t < T_STEPS; t++) {
        // prefetch next step's gi (independent of the wait)
        float ngr = 0.f, ngz = 0.f, ngn = 0.f;
        if (t + 1 < T_STEPS) {
            const float* p = g_gi + (size_t)(t + 1) * G3;
            ngr = __ldg(p + j); ngz = __ldg(p + HID + j); ngn = __ldg(p + 2 * HID + j);
        }

        if (t > 0) {
            if (wid == 0) {
                // warp 0 polls all 128 flags (4 per lane) — R1-exact volatile loop
                for (;;) {
                    int f0 = vflags[lane];
                    int f1 = vflags[lane + 32];
                    int f2 = vflags[lane + 64];
                    int f3 = vflags[lane + 96];
                    int m = min(min(f0, f1), min(f2, f3));
                    if (__all_sync(0xffffffffu, m >= t)) break;
                }
                // (consumer threadfence removed: staging below is ld.cg from L2)
            }
            __syncthreads();
            // stage h_t (L1 bypass: written by other SMs)
            const float4* src = reinterpret_cast<const float4*>(g_hex[t & 1]);
            reinterpret_cast<float4*>(hs)[tid] = __ldcg(src + tid);
            __syncthreads();   // all warps staged before anyone reads full hs
        }

        // 3 dot products of length 1024 via packed f32x2 FMA
        unsigned long long ar2 = 0ULL, az2 = 0ULL, an2 = 0ULL;
        const ulonglong2* h2 = reinterpret_cast<const ulonglong2*>(hs);
#pragma unroll
        for (int i = 0; i < 8; i++) {
            ulonglong2 hv = h2[lane + 32 * i];
            ar2 = ffma2(wr2[2 * i], hv.x, ar2);
            ar2 = ffma2(wr2[2 * i + 1], hv.y, ar2);
            az2 = ffma2(wz2[2 * i], hv.x, az2);
            az2 = ffma2(wz2[2 * i + 1], hv.y, az2);
            an2 = ffma2(wn2[2 * i], hv.x, an2);
            an2 = ffma2(wn2[2 * i + 1], hv.y, an2);
        }
        float2 fr = unpack2(ar2), fz = unpack2(az2), fn = unpack2(an2);
        float ar = fr.x + fr.y, az = fz.x + fz.y, an = fn.x + fn.y;
#pragma unroll
        for (int o = 16; o > 0; o >>= 1) {
            ar += __shfl_xor_sync(0xffffffffu, ar, o);
            az += __shfl_xor_sync(0xffffffffu, az, o);
            an += __shfl_xor_sync(0xffffffffu, an, o);
        }

        float r    = fsig(gr + ar + br);
        float zz   = fsig(gz + az + bz);
        float n    = ftanh(gn + r * (an + bn));
        float hold = hs[j];
        float hnew = n + zz * (hold - n);   // (1-z)*n + z*h

        if (lane == 0) {
            out[(size_t)t * HID + j] = hnew;
            g_hex[(t + 1) & 1][j] = hnew;    // plain store (R1-exact)
        }

        gr = ngr; gz = ngz; gn = ngn;

        __syncthreads();                     // all warps published
        if (tid == 0) {
            __threadfence();                 // R1-exact producer fence
            vflags[bid] = t + 1;             // volatile release flag
        }
    }
}

// ---------------- launch ----------------
extern "C" void kernel_launch(void* const* d_in, const int* in_sizes, int n_in,
                              void* d_out, int out_size) {
    const float* obs   = (const float*)d_in[0];
    const float* act   = (const float*)d_in[1];
    const float* enc_w = (const float*)d_in[2];
    const float* enc_b = (const float*)d_in[3];
    const float* w_ih  = (const float*)d_in[4];
    const float* w_hh  = (const float*)d_in[5];
    const float* b_ih  = (const float*)d_in[6];
    const float* b_hh  = (const float*)d_in[7];
    float* out = (float*)d_out;

    init_kernel<<<1, 128>>>();
    enc_kernel<<<T_STEPS / 64, 256>>>(obs, enc_w, enc_b);
    pack_act<<<(T_STEPS * ACT) / 256, 256>>>(act);
    gemm_gi<<<dim3(G3 / 128, T_STEPS / 64), 256>>>(w_ih, b_ih);
    recur_kernel<<<NCTA, 256>>>(w_hh, b_hh, out);
}